// round 13
// baseline (speedup 1.0000x reference)
#include <cuda_runtime.h>
#include <cuda_bf16.h>

// Problem shape (fixed by the reference)
#define NWALK 4096
#define NIN   24      // NPART*NDIM
#define HID   256
#define BLOCK 128
#define STR   28      // padded smem stride (words): conflict-free LDS.128 phases

// Prepped image = exact smem layout, 8192 floats = 32KB:
//  [0, HID*STR): padded W1^T, img[j*STR + i] = W1[i*HID + j]
//  [HID*STR, +HID float4): P[j] = (b1_j, W2_j, -2*S_j*W2_j, 0)
#define IMG_FLOATS (HID * STR + HID * 4)     // 7168 + 1024 = 8192
__device__ float gImg[IMG_FLOATS];

// ---- packed f32x2 helpers (sm_100a FFMA2 path; ptxas never auto-fuses) ----
__device__ __forceinline__ unsigned long long pk2(float lo, float hi) {
    unsigned long long r;
    asm("mov.b64 %0, {%1, %2};" : "=l"(r) : "f"(lo), "f"(hi));
    return r;
}
__device__ __forceinline__ void upk2(unsigned long long v, float& lo, float& hi) {
    asm("mov.b64 {%0, %1}, %2;" : "=f"(lo), "=f"(hi) : "l"(v));
}
__device__ __forceinline__ unsigned long long ffma2(unsigned long long a,
                                                    unsigned long long b,
                                                    unsigned long long c) {
    unsigned long long d;
    asm("fma.rn.f32x2 %0, %1, %2, %3;" : "=l"(d) : "l"(a), "l"(b), "l"(c));
    return d;
}
__device__ __forceinline__ unsigned long long fadd2(unsigned long long a,
                                                    unsigned long long b) {
    unsigned long long d;
    asm("add.rn.f32x2 %0, %1, %2;" : "=l"(d) : "l"(a), "l"(b));
    return d;
}
__device__ __forceinline__ float tanh_hw(float a) {
    float h;
    asm("tanh.approx.f32 %0, %1;" : "=f"(h) : "f"(a));
    return h;
}

__global__ __launch_bounds__(HID)
void prep_kernel(const float* __restrict__ W1,
                 const float* __restrict__ b1,
                 const float* __restrict__ W2)
{
    const int j = threadIdx.x;                 // one column per thread, 256 threads
    float w[NIN];
    float s = 0.f;
    #pragma unroll
    for (int i = 0; i < NIN; i++) {            // coalesced over j
        w[i] = W1[i * HID + j];
        s = fmaf(w[i], w[i], s);
    }
    #pragma unroll
    for (int i = 0; i < NIN; i++) gImg[j * STR + i] = w[i];
    #pragma unroll
    for (int i = NIN; i < STR; i++) gImg[j * STR + i] = 0.f;   // zero padding
    const float w2 = W2[j];
    float4* P = reinterpret_cast<float4*>(gImg + HID * STR);
    P[j] = make_float4(b1[j], w2, -2.f * s * w2, 0.f);
}

__global__ __launch_bounds__(BLOCK)
void kin_kernel(const float* __restrict__ x,
                float* __restrict__ out)
{
    __shared__ float smemAll[IMG_FLOATS];      // 32KB: W1^T padded + P
    float*  sW1t = smemAll;
    const float4* sP = reinterpret_cast<const float4*>(smemAll + HID * STR);

    const int tid = threadIdx.x;

    // ---- Preamble: straight 32KB image copy, 16-deep MLP, fully coalesced ----
    {
        const float4* src = reinterpret_cast<const float4*>(gImg);
        float4* dst = reinterpret_cast<float4*>(smemAll);
        #pragma unroll
        for (int t = 0; t < IMG_FLOATS / 4 / BLOCK; t++)   // 16 iterations
            dst[t * BLOCK + tid] = __ldg(&src[t * BLOCK + tid]);
    }
    __syncthreads();

    // ---- Main: one WARP per walker pair; halves split the columns ----
    const int wid  = tid >> 5;                 // warp in block (0..3)
    const int lid  = tid & 31;
    const int half = lid >> 4;                 // 0: cols 0-127, 1: cols 128-255
    const int sub  = lid & 15;
    const int pair = blockIdx.x * (BLOCK / 32) + wid;

    // Both walkers' z (each 96B, 16B-aligned); whole warp loads same -> broadcast
    const ulonglong2* zA4 = reinterpret_cast<const ulonglong2*>(x + (2 * pair)     * NIN);
    const ulonglong2* zB4 = reinterpret_cast<const ulonglong2*>(x + (2 * pair + 1) * NIN);
    unsigned long long zA[12], zB[12];
    #pragma unroll
    for (int c = 0; c < 6; c++) {
        ulonglong2 va = zA4[c]; zA[2*c] = va.x; zA[2*c+1] = va.y;
        ulonglong2 vb = zB4[c]; zB[2*c] = vb.x; zB[2*c+1] = vb.y;
    }

    unsigned long long gA[12], gB[12];
    #pragma unroll
    for (int q = 0; q < 12; q++) { gA[q] = 0ull; gB[q] = 0ull; }
    float lapA = 0.f, lapB = 0.f;

    const int jbase = (half << 7) + sub;       // this lane's column stream

    #pragma unroll 4
    for (int jj = 0; jj < 8; jj++) {           // 128 cols / 16 lanes
        const int j = jbase + (jj << 4);
        const float* wc = &sW1t[j * STR];

        unsigned long long w_pk[12];
        #pragma unroll
        for (int c = 0; c < 6; c++) {
            const float4 v = *reinterpret_cast<const float4*>(wc + 4 * c);  // LDS.128
            w_pk[2*c]     = pk2(v.x, v.y);
            w_pk[2*c + 1] = pk2(v.z, v.w);
        }
        const float4 p = sP[j];                // (b1, W2, -2*S*W2, 0)

        // dots for both walkers (packed over i): 12 FFMA2 each
        unsigned long long aA0 = pk2(p.x, 0.f), aA1 = 0ull, aA2 = 0ull, aA3 = 0ull;
        unsigned long long aB0 = pk2(p.x, 0.f), aB1 = 0ull, aB2 = 0ull, aB3 = 0ull;
        #pragma unroll
        for (int q = 0; q < 12; q += 4) {
            aA0 = ffma2(zA[q],     w_pk[q],     aA0);
            aA1 = ffma2(zA[q + 1], w_pk[q + 1], aA1);
            aA2 = ffma2(zA[q + 2], w_pk[q + 2], aA2);
            aA3 = ffma2(zA[q + 3], w_pk[q + 3], aA3);
            aB0 = ffma2(zB[q],     w_pk[q],     aB0);
            aB1 = ffma2(zB[q + 1], w_pk[q + 1], aB1);
            aB2 = ffma2(zB[q + 2], w_pk[q + 2], aB2);
            aB3 = ffma2(zB[q + 3], w_pk[q + 3], aB3);
        }
        float loA, hiA, loB, hiB;
        upk2(fadd2(fadd2(aA0, aA1), fadd2(aA2, aA3)), loA, hiA);
        upk2(fadd2(fadd2(aB0, aB1), fadd2(aB2, aB3)), loB, hiB);

        // hardware tanh; om = 1-h^2 (non-saturated regime)
        const float hA  = tanh_hw(loA + hiA);
        const float hB  = tanh_hw(loB + hiB);
        const float omA = fmaf(-hA, hA, 1.f);
        const float omB = fmaf(-hB, hB, 1.f);
        const float uA  = omA * p.y;
        const float uB  = omB * p.y;
        lapA = fmaf(omA * hA, p.z, lapA);
        lapB = fmaf(omB * hB, p.z, lapB);

        const unsigned long long dA = pk2(uA, uA);
        const unsigned long long dB = pk2(uB, uB);
        #pragma unroll
        for (int q = 0; q < 12; q++) {
            gA[q] = ffma2(w_pk[q], dA, gA[q]);
            gB[q] = ffma2(w_pk[q], dB, gB[q]);
        }
    }

    // Full-warp butterfly (5 steps): merges lanes AND the two column halves
    #pragma unroll
    for (int ofs = 1; ofs < 32; ofs <<= 1) {
        #pragma unroll
        for (int q = 0; q < 12; q++) {
            gA[q] = fadd2(gA[q], __shfl_xor_sync(0xffffffffu, gA[q], ofs));
            gB[q] = fadd2(gB[q], __shfl_xor_sync(0xffffffffu, gB[q], ofs));
        }
        lapA += __shfl_xor_sync(0xffffffffu, lapA, ofs);
        lapB += __shfl_xor_sync(0xffffffffu, lapB, ofs);
    }

    if (lid == 0) {
        unsigned long long gsA = 0ull, gsB = 0ull;
        #pragma unroll
        for (int q = 0; q < 12; q++) {
            gsA = ffma2(gA[q], gA[q], gsA);
            gsB = ffma2(gB[q], gB[q], gsB);
        }
        float la, ha, lb, hb;
        upk2(gsA, la, ha);
        upk2(gsB, lb, hb);
        float2 res;
        res.x = -0.5f * (lapA + (la + ha));
        res.y = -0.5f * (lapB + (lb + hb));
        *reinterpret_cast<float2*>(out + 2 * pair) = res;    // 8B-aligned
    }
}

extern "C" void kernel_launch(void* const* d_in, const int* in_sizes, int n_in,
                              void* d_out, int out_size)
{
    // metadata order: x [4096*8*3], W1 [24*256], b1 [256], W2 [256], b2 [1]
    const float* x  = (const float*)d_in[0];
    const float* W1 = (const float*)d_in[1];
    const float* b1 = (const float*)d_in[2];
    const float* W2 = (const float*)d_in[3];
    float* out = (float*)d_out;

    prep_kernel<<<1, HID>>>(W1, b1, W2);
    // 2048 pairs, 4 pairs (warps) per block -> 512 blocks
    kin_kernel<<<(NWALK / 2) / (BLOCK / 32), BLOCK>>>(x, out);
}

// round 14
// speedup vs baseline: 1.5981x; 1.5981x over previous
#include <cuda_runtime.h>
#include <cuda_bf16.h>

// Problem shape (fixed by the reference)
#define NWALK 4096
#define NIN   24      // NPART*NDIM
#define HID   256
#define TPW   16      // lanes per walker-pair group
#define BLOCK 256
#define STR   28      // padded smem stride (words): conflict-free LDS.128 phases

// ---- packed f32x2 helpers (sm_100a FFMA2 path; ptxas never auto-fuses) ----
__device__ __forceinline__ unsigned long long pk2(float lo, float hi) {
    unsigned long long r;
    asm("mov.b64 %0, {%1, %2};" : "=l"(r) : "f"(lo), "f"(hi));
    return r;
}
__device__ __forceinline__ void upk2(unsigned long long v, float& lo, float& hi) {
    asm("mov.b64 {%0, %1}, %2;" : "=f"(lo), "=f"(hi) : "l"(v));
}
__device__ __forceinline__ unsigned long long ffma2(unsigned long long a,
                                                    unsigned long long b,
                                                    unsigned long long c) {
    unsigned long long d;
    asm("fma.rn.f32x2 %0, %1, %2, %3;" : "=l"(d) : "l"(a), "l"(b), "l"(c));
    return d;
}
__device__ __forceinline__ unsigned long long fadd2(unsigned long long a,
                                                    unsigned long long b) {
    unsigned long long d;
    asm("add.rn.f32x2 %0, %1, %2;" : "=l"(d) : "l"(a), "l"(b));
    return d;
}
__device__ __forceinline__ float tanh_hw(float a) {
    float h;
    asm("tanh.approx.f32 %0, %1;" : "=f"(h) : "f"(a));
    return h;
}

__global__ __launch_bounds__(BLOCK, 1)
void kin_kernel(const float* __restrict__ x,
                const float* __restrict__ W1,
                const float* __restrict__ b1,
                const float* __restrict__ W2,
                float* __restrict__ out)
{
    __shared__ float  sW1t[HID * STR];   // [j][i], padded: 28KB
    __shared__ float4 sP[HID];           // (b1_j, W2_j, -2*S_j*W2_j, 0): 4KB

    const int tid = threadIdx.x;

    // ---- Preamble: coalesced transpose fill (24 LDG/thread), once per SM ----
    #pragma unroll
    for (int t = 0; t < (NIN * HID) / BLOCK; t++) {
        const int k = t * BLOCK + tid;                  // k = i*HID + j
        const int i = k >> 8;
        const int j = k & (HID - 1);
        sW1t[j * STR + i] = W1[k];
    }
    {   // per-column constants: one column per thread
        const float b0 = b1[tid];
        const float w0 = W2[tid];
        __syncthreads();                                // sW1t ready
        float s0 = 0.f;
        #pragma unroll
        for (int i = 0; i < NIN; i++) {
            const float a = sW1t[tid * STR + i];
            s0 = fmaf(a, a, s0);
        }
        sP[tid] = make_float4(b0, w0, -2.f * s0 * w0, 0.f);
    }
    __syncthreads();

    // ---- Main: 2 walkers per 16-lane group (R11 structure) ----
    const int gt    = blockIdx.x * BLOCK + tid;
    const int group = gt >> 4;
    const int sub   = gt & (TPW - 1);

    const ulonglong2* zA4 = reinterpret_cast<const ulonglong2*>(x + (2 * group)     * NIN);
    const ulonglong2* zB4 = reinterpret_cast<const ulonglong2*>(x + (2 * group + 1) * NIN);
    unsigned long long zA[12], zB[12];
    #pragma unroll
    for (int c = 0; c < 6; c++) {
        ulonglong2 va = zA4[c]; zA[2*c] = va.x; zA[2*c+1] = va.y;
        ulonglong2 vb = zB4[c]; zB[2*c] = vb.x; zB[2*c+1] = vb.y;
    }

    unsigned long long gA[12], gB[12];
    #pragma unroll
    for (int q = 0; q < 12; q++) { gA[q] = 0ull; gB[q] = 0ull; }
    float lapA = 0.f, lapB = 0.f;

    // Software pipeline: prefetch column (jj+1)'s weights before jj's math.
    unsigned long long wc_pk[12];        // current weights
    float4 pc;                           // current constants
    {
        const float* wp = &sW1t[sub * STR];
        #pragma unroll
        for (int c = 0; c < 6; c++) {
            const float4 v = *reinterpret_cast<const float4*>(wp + 4 * c);  // LDS.128
            wc_pk[2*c]     = pk2(v.x, v.y);
            wc_pk[2*c + 1] = pk2(v.z, v.w);
        }
        pc = sP[sub];
    }

    #pragma unroll 4
    for (int jj = 0; jj < HID / TPW; jj++) {
        // -- prefetch next column's data (overlaps with math below) --
        unsigned long long wn_pk[12];
        float4 pn;
        if (jj < HID / TPW - 1) {
            const int jn = ((jj + 1) << 4) + sub;
            const float* wp = &sW1t[jn * STR];
            #pragma unroll
            for (int c = 0; c < 6; c++) {
                const float4 v = *reinterpret_cast<const float4*>(wp + 4 * c);
                wn_pk[2*c]     = pk2(v.x, v.y);
                wn_pk[2*c + 1] = pk2(v.z, v.w);
            }
            pn = sP[jn];
        }

        // -- math on current column --
        unsigned long long aA0 = pk2(pc.x, 0.f), aA1 = 0ull, aA2 = 0ull, aA3 = 0ull;
        unsigned long long aB0 = pk2(pc.x, 0.f), aB1 = 0ull, aB2 = 0ull, aB3 = 0ull;
        #pragma unroll
        for (int q = 0; q < 12; q += 4) {
            aA0 = ffma2(zA[q],     wc_pk[q],     aA0);
            aA1 = ffma2(zA[q + 1], wc_pk[q + 1], aA1);
            aA2 = ffma2(zA[q + 2], wc_pk[q + 2], aA2);
            aA3 = ffma2(zA[q + 3], wc_pk[q + 3], aA3);
            aB0 = ffma2(zB[q],     wc_pk[q],     aB0);
            aB1 = ffma2(zB[q + 1], wc_pk[q + 1], aB1);
            aB2 = ffma2(zB[q + 2], wc_pk[q + 2], aB2);
            aB3 = ffma2(zB[q + 3], wc_pk[q + 3], aB3);
        }
        float loA, hiA, loB, hiB;
        upk2(fadd2(fadd2(aA0, aA1), fadd2(aA2, aA3)), loA, hiA);
        upk2(fadd2(fadd2(aB0, aB1), fadd2(aB2, aB3)), loB, hiB);

        const float hA  = tanh_hw(loA + hiA);
        const float hB  = tanh_hw(loB + hiB);
        const float omA = fmaf(-hA, hA, 1.f);
        const float omB = fmaf(-hB, hB, 1.f);
        const float uA  = omA * pc.y;
        const float uB  = omB * pc.y;
        lapA = fmaf(omA * hA, pc.z, lapA);
        lapB = fmaf(omB * hB, pc.z, lapB);

        const unsigned long long dA = pk2(uA, uA);
        const unsigned long long dB = pk2(uB, uB);
        #pragma unroll
        for (int q = 0; q < 12; q++) {
            gA[q] = ffma2(wc_pk[q], dA, gA[q]);
            gB[q] = ffma2(wc_pk[q], dB, gB[q]);
        }

        // -- rotate pipeline --
        if (jj < HID / TPW - 1) {
            #pragma unroll
            for (int q = 0; q < 12; q++) wc_pk[q] = wn_pk[q];
            pc = pn;
        }
    }

    // Butterfly reduction across the 16 lanes of this group
    #pragma unroll
    for (int ofs = 1; ofs < TPW; ofs <<= 1) {
        #pragma unroll
        for (int q = 0; q < 12; q++) {
            gA[q] = fadd2(gA[q], __shfl_xor_sync(0xffffffffu, gA[q], ofs));
            gB[q] = fadd2(gB[q], __shfl_xor_sync(0xffffffffu, gB[q], ofs));
        }
        lapA += __shfl_xor_sync(0xffffffffu, lapA, ofs);
        lapB += __shfl_xor_sync(0xffffffffu, lapB, ofs);
    }

    if (sub == 0) {
        unsigned long long gsA = 0ull, gsB = 0ull;
        #pragma unroll
        for (int q = 0; q < 12; q++) {
            gsA = ffma2(gA[q], gA[q], gsA);
            gsB = ffma2(gB[q], gB[q], gsB);
        }
        float la, ha, lb, hb;
        upk2(gsA, la, ha);
        upk2(gsB, lb, hb);
        float2 res;
        res.x = -0.5f * (lapA + (la + ha));
        res.y = -0.5f * (lapB + (lb + hb));
        *reinterpret_cast<float2*>(out + 2 * group) = res;   // 8B-aligned
    }
}

extern "C" void kernel_launch(void* const* d_in, const int* in_sizes, int n_in,
                              void* d_out, int out_size)
{
    // metadata order: x [4096*8*3], W1 [24*256], b1 [256], W2 [256], b2 [1]
    const float* x  = (const float*)d_in[0];
    const float* W1 = (const float*)d_in[1];
    const float* b1 = (const float*)d_in[2];
    const float* W2 = (const float*)d_in[3];
    float* out = (float*)d_out;

    // Single graph node: 128 blocks x 256 threads; 32 walkers per block.
    // 128 blocks <= 148 SMs: one block per SM, even wave, half the preambles.
    kin_kernel<<<NWALK / 32, BLOCK>>>(x, W1, b1, W2, out);
}

// round 15
// speedup vs baseline: 1.7509x; 1.0956x over previous
#include <cuda_runtime.h>
#include <cuda_bf16.h>

// Problem shape (fixed by the reference)
#define NWALK 4096
#define NIN   24      // NPART*NDIM
#define HID   256
#define TPW   16      // lanes per walker-pair group
#define BLOCK 256
#define STR   28      // padded smem stride (words): conflict-free LDS.128 phases

// ---- packed f32x2 helpers (sm_100a FFMA2 path; ptxas never auto-fuses) ----
__device__ __forceinline__ unsigned long long pk2(float lo, float hi) {
    unsigned long long r;
    asm("mov.b64 %0, {%1, %2};" : "=l"(r) : "f"(lo), "f"(hi));
    return r;
}
__device__ __forceinline__ void upk2(unsigned long long v, float& lo, float& hi) {
    asm("mov.b64 {%0, %1}, %2;" : "=f"(lo), "=f"(hi) : "l"(v));
}
__device__ __forceinline__ unsigned long long ffma2(unsigned long long a,
                                                    unsigned long long b,
                                                    unsigned long long c) {
    unsigned long long d;
    asm("fma.rn.f32x2 %0, %1, %2, %3;" : "=l"(d) : "l"(a), "l"(b), "l"(c));
    return d;
}
__device__ __forceinline__ unsigned long long fadd2(unsigned long long a,
                                                    unsigned long long b) {
    unsigned long long d;
    asm("add.rn.f32x2 %0, %1, %2;" : "=l"(d) : "l"(a), "l"(b));
    return d;
}
__device__ __forceinline__ float tanh_hw(float a) {
    float h;
    asm("tanh.approx.f32 %0, %1;" : "=f"(h) : "f"(a));
    return h;
}

__global__ __launch_bounds__(BLOCK, 1)
void kin_kernel(const float* __restrict__ x,
                const float* __restrict__ W1,
                const float* __restrict__ b1,
                const float* __restrict__ W2,
                float* __restrict__ out)
{
    __shared__ float  sW1t[HID * STR];   // [j][i], padded: 28KB
    __shared__ float4 sP[HID];           // (b1_j, W2_j, -2*S_j*W2_j, 0): 4KB

    const int tid = threadIdx.x;

    // ---- Hoist walker z LDGs: latency hides under the preamble burst ----
    const int gt    = blockIdx.x * BLOCK + tid;
    const int group = gt >> 4;
    const int sub   = gt & (TPW - 1);
    const ulonglong2* zA4 = reinterpret_cast<const ulonglong2*>(x + (2 * group)     * NIN);
    const ulonglong2* zB4 = reinterpret_cast<const ulonglong2*>(x + (2 * group + 1) * NIN);
    unsigned long long zA[12], zB[12];
    #pragma unroll
    for (int c = 0; c < 6; c++) {
        ulonglong2 va = zA4[c]; zA[2*c] = va.x; zA[2*c+1] = va.y;
        ulonglong2 vb = zB4[c]; zB[2*c] = vb.x; zB[2*c+1] = vb.y;
    }

    // ---- Preamble: coalesced transpose fill (24 LDG/thread), once per SM ----
    #pragma unroll
    for (int t = 0; t < (NIN * HID) / BLOCK; t++) {
        const int k = t * BLOCK + tid;                  // k = i*HID + j
        const int i = k >> 8;
        const int j = k & (HID - 1);
        sW1t[j * STR + i] = W1[k];
    }
    {   // per-column constants: one column per thread
        const float b0 = b1[tid];
        const float w0 = W2[tid];
        __syncthreads();                                // sW1t ready
        float s0 = 0.f;
        #pragma unroll
        for (int i = 0; i < NIN; i++) {
            const float a = sW1t[tid * STR + i];
            s0 = fmaf(a, a, s0);
        }
        sP[tid] = make_float4(b0, w0, -2.f * s0 * w0, 0.f);
    }
    __syncthreads();

    // ---- Main: 2 walkers x 2 columns per lane-iteration (4 indep chains) ----
    unsigned long long gA[12], gB[12];
    #pragma unroll
    for (int q = 0; q < 12; q++) { gA[q] = 0ull; gB[q] = 0ull; }
    float lapA = 0.f, lapB = 0.f;

    #pragma unroll 2
    for (int jj = 0; jj < HID / TPW / 2; jj++) {        // 8 iterations
        const int j0 = (jj << 4) + sub;                 // cols 0..127 stream
        const int j1 = j0 + 128;                        // cols 128..255 stream
        const float* wp0 = &sW1t[j0 * STR];
        const float* wp1 = &sW1t[j1 * STR];

        // 14 back-to-back LDS.128 (natural MLP burst)
        unsigned long long w0[12], w1[12];
        #pragma unroll
        for (int c = 0; c < 6; c++) {
            const float4 v0 = *reinterpret_cast<const float4*>(wp0 + 4 * c);
            const float4 v1 = *reinterpret_cast<const float4*>(wp1 + 4 * c);
            w0[2*c] = pk2(v0.x, v0.y); w0[2*c + 1] = pk2(v0.z, v0.w);
            w1[2*c] = pk2(v1.x, v1.y); w1[2*c + 1] = pk2(v1.z, v1.w);
        }
        const float4 p0 = sP[j0];
        const float4 p1 = sP[j1];

        // 4 independent dots (A,B) x (j0,j1): 2 packed accumulators each
        unsigned long long dA0a = pk2(p0.x, 0.f), dA0b = 0ull;
        unsigned long long dB0a = pk2(p0.x, 0.f), dB0b = 0ull;
        unsigned long long dA1a = pk2(p1.x, 0.f), dA1b = 0ull;
        unsigned long long dB1a = pk2(p1.x, 0.f), dB1b = 0ull;
        #pragma unroll
        for (int q = 0; q < 12; q += 2) {
            dA0a = ffma2(zA[q],     w0[q],     dA0a);
            dA0b = ffma2(zA[q + 1], w0[q + 1], dA0b);
            dB0a = ffma2(zB[q],     w0[q],     dB0a);
            dB0b = ffma2(zB[q + 1], w0[q + 1], dB0b);
            dA1a = ffma2(zA[q],     w1[q],     dA1a);
            dA1b = ffma2(zA[q + 1], w1[q + 1], dA1b);
            dB1a = ffma2(zB[q],     w1[q],     dB1a);
            dB1b = ffma2(zB[q + 1], w1[q + 1], dB1b);
        }
        float lo, hi;
        upk2(fadd2(dA0a, dA0b), lo, hi); const float aA0 = lo + hi;
        upk2(fadd2(dB0a, dB0b), lo, hi); const float aB0 = lo + hi;
        upk2(fadd2(dA1a, dA1b), lo, hi); const float aA1 = lo + hi;
        upk2(fadd2(dB1a, dB1b), lo, hi); const float aB1 = lo + hi;

        // 4 independent tanh chains
        const float hA0 = tanh_hw(aA0), hB0 = tanh_hw(aB0);
        const float hA1 = tanh_hw(aA1), hB1 = tanh_hw(aB1);
        const float omA0 = fmaf(-hA0, hA0, 1.f), omB0 = fmaf(-hB0, hB0, 1.f);
        const float omA1 = fmaf(-hA1, hA1, 1.f), omB1 = fmaf(-hB1, hB1, 1.f);
        const float uA0 = omA0 * p0.y, uB0 = omB0 * p0.y;
        const float uA1 = omA1 * p1.y, uB1 = omB1 * p1.y;
        lapA = fmaf(omA0 * hA0, p0.z, lapA);
        lapB = fmaf(omB0 * hB0, p0.z, lapB);
        lapA = fmaf(omA1 * hA1, p1.z, lapA);
        lapB = fmaf(omB1 * hB1, p1.z, lapB);

        // gradient accumulation: 48 FFMA2, 24 independent chains
        const unsigned long long eA0 = pk2(uA0, uA0), eB0 = pk2(uB0, uB0);
        const unsigned long long eA1 = pk2(uA1, uA1), eB1 = pk2(uB1, uB1);
        #pragma unroll
        for (int q = 0; q < 12; q++) {
            gA[q] = ffma2(w0[q], eA0, gA[q]);
            gB[q] = ffma2(w0[q], eB0, gB[q]);
            gA[q] = ffma2(w1[q], eA1, gA[q]);
            gB[q] = ffma2(w1[q], eB1, gB[q]);
        }
    }

    // Butterfly reduction across the 16 lanes of this group
    #pragma unroll
    for (int ofs = 1; ofs < TPW; ofs <<= 1) {
        #pragma unroll
        for (int q = 0; q < 12; q++) {
            gA[q] = fadd2(gA[q], __shfl_xor_sync(0xffffffffu, gA[q], ofs));
            gB[q] = fadd2(gB[q], __shfl_xor_sync(0xffffffffu, gB[q], ofs));
        }
        lapA += __shfl_xor_sync(0xffffffffu, lapA, ofs);
        lapB += __shfl_xor_sync(0xffffffffu, lapB, ofs);
    }

    if (sub == 0) {
        unsigned long long gsA = 0ull, gsB = 0ull;
        #pragma unroll
        for (int q = 0; q < 12; q++) {
            gsA = ffma2(gA[q], gA[q], gsA);
            gsB = ffma2(gB[q], gB[q], gsB);
        }
        float la, ha, lb, hb;
        upk2(gsA, la, ha);
        upk2(gsB, lb, hb);
        float2 res;
        res.x = -0.5f * (lapA + (la + ha));
        res.y = -0.5f * (lapB + (lb + hb));
        *reinterpret_cast<float2*>(out + 2 * group) = res;   // 8B-aligned
    }
}

extern "C" void kernel_launch(void* const* d_in, const int* in_sizes, int n_in,
                              void* d_out, int out_size)
{
    // metadata order: x [4096*8*3], W1 [24*256], b1 [256], W2 [256], b2 [1]
    const float* x  = (const float*)d_in[0];
    const float* W1 = (const float*)d_in[1];
    const float* b1 = (const float*)d_in[2];
    const float* W2 = (const float*)d_in[3];
    float* out = (float*)d_out;

    // Single graph node: 128 blocks x 256 threads; 32 walkers per block.
    kin_kernel<<<NWALK / 32, BLOCK>>>(x, W1, b1, W2, out);
}